// round 1
// baseline (speedup 1.0000x reference)
#include <cuda_runtime.h>

#define HID     30
#define NPAIR   15      // j-pairs (30 is even: exact)
#define SEQLEN  784
#define NCLS    10
#define WSTRIDE 16      // u64 stride per k-row in shared (128B, aligned)

typedef unsigned long long u64;

// ---- packed f32x2 helpers (Blackwell FFMA2 path) ----
__device__ __forceinline__ u64 dup2(float v) {
    u64 r; asm("mov.b64 %0, {%1,%1};" : "=l"(r) : "f"(v)); return r;
}
__device__ __forceinline__ u64 pk2(float lo, float hi) {
    u64 r; asm("mov.b64 %0, {%1,%2};" : "=l"(r) : "f"(lo), "f"(hi)); return r;
}
__device__ __forceinline__ float2 up2(u64 v) {
    float2 f; asm("mov.b64 {%0,%1}, %2;" : "=f"(f.x), "=f"(f.y) : "l"(v)); return f;
}
__device__ __forceinline__ u64 fma2(u64 a, u64 b, u64 c) {
    u64 d; asm("fma.rn.f32x2 %0, %1, %2, %3;" : "=l"(d) : "l"(a), "l"(b), "l"(c)); return d;
}
__device__ __forceinline__ u64 mul2(u64 a, u64 b) {
    u64 d; asm("mul.rn.f32x2 %0, %1, %2;" : "=l"(d) : "l"(a), "l"(b)); return d;
}

// modReLU: sign(z) * relu(|z| + b). r = max(|z|+b, 0) >= 0, so OR in z's sign bit (1 LOP3).
__device__ __forceinline__ float mrelu(float z, float b) {
    float t = fabsf(z) + b;        // FADD with |.| operand modifier
    float r = fmaxf(t, 0.0f);      // FMNMX
    unsigned u = __float_as_uint(r) | (__float_as_uint(z) & 0x80000000u);  // LOP3
    return __uint_as_float(u);
}

__global__ __launch_bounds__(128, 1)
void rnn_modrelu_kernel(const float* __restrict__ inputs,
                        const float* __restrict__ W_ih,
                        const float* __restrict__ W_hh,
                        const float* __restrict__ b_mod,
                        const float* __restrict__ W_lin,
                        const float* __restrict__ b_lin,
                        float* __restrict__ out, int B)
{
    // sW[k*WSTRIDE + p] = (W_hh[2p][k], W_hh[2p+1][k])  -- j-pair packed, k-major rows
    __shared__ __align__(16) u64 sW[HID * WSTRIDE];
    __shared__ float sWlin[NCLS * HID];
    __shared__ float sblin[NCLS];
    __shared__ float sWih[HID];
    __shared__ float sbm[HID];

    const int tid = threadIdx.x;
    for (int i = tid; i < HID * NPAIR; i += blockDim.x) {
        int k = i / NPAIR, p = i % NPAIR;
        sW[k * WSTRIDE + p] = pk2(W_hh[(2 * p) * HID + k], W_hh[(2 * p + 1) * HID + k]);
    }
    for (int i = tid; i < NCLS * HID; i += blockDim.x) sWlin[i] = W_lin[i];
    for (int i = tid; i < HID; i += blockDim.x) { sWih[i] = W_ih[i]; sbm[i] = b_mod[i]; }
    for (int i = tid; i < NCLS; i += blockDim.x) sblin[i] = b_lin[i];
    __syncthreads();

    const int row = blockIdx.x * blockDim.x + tid;
    if (row >= B) return;

    // hoisted loop-invariants into registers
    u64 wih2[NPAIR];
#pragma unroll
    for (int p = 0; p < NPAIR; p++) wih2[p] = pk2(sWih[2 * p], sWih[2 * p + 1]);
    float bm[HID];
#pragma unroll
    for (int j = 0; j < HID; j++) bm[j] = sbm[j];

    float h[HID];
#pragma unroll
    for (int j = 0; j < HID; j++) h[j] = 0.0f;

    const float* xrow = inputs + (long)row * SEQLEN;
    float x = xrow[0];

    for (int t = 0; t < SEQLEN; ++t) {
        float xn = (t < SEQLEN - 1) ? __ldg(xrow + t + 1) : 0.0f;  // prefetch next step

        u64 xd = dup2(x);
        u64 z[NPAIR];
#pragma unroll
        for (int p = 0; p < NPAIR; p++) z[p] = mul2(xd, wih2[p]);   // z = x * W_ih (paired)

#pragma unroll
        for (int k = 0; k < HID; k++) {
            u64 hd = dup2(h[k]);
            const u64* wr = &sW[k * WSTRIDE];
            const ulonglong2* wr2 = (const ulonglong2*)wr;          // 16B-aligned
#pragma unroll
            for (int q = 0; q < 7; q++) {                           // 7x LDS.128
                ulonglong2 w = wr2[q];
                z[2 * q]     = fma2(hd, w.x, z[2 * q]);
                z[2 * q + 1] = fma2(hd, w.y, z[2 * q + 1]);
            }
            z[14] = fma2(hd, wr[14], z[14]);                        // 1x LDS.64
        }

#pragma unroll
        for (int p = 0; p < NPAIR; p++) {
            float2 zz = up2(z[p]);
            h[2 * p]     = mrelu(zz.x, bm[2 * p]);
            h[2 * p + 1] = mrelu(zz.y, bm[2 * p + 1]);
        }
        x = xn;
    }

    // logits: out[row] = h @ W_lin^T + b_lin
    float* orow = out + (long)row * NCLS;
#pragma unroll
    for (int c = 0; c < NCLS; c++) {
        float acc = sblin[c];
#pragma unroll
        for (int j = 0; j < HID; j++) acc = fmaf(h[j], sWlin[c * HID + j], acc);
        orow[c] = acc;
    }
}

extern "C" void kernel_launch(void* const* d_in, const int* in_sizes, int n_in,
                              void* d_out, int out_size)
{
    const float* inputs = (const float*)d_in[0];
    const float* W_ih   = (const float*)d_in[1];
    const float* W_hh   = (const float*)d_in[2];
    const float* b_mod  = (const float*)d_in[3];
    const float* W_lin  = (const float*)d_in[4];
    const float* b_lin  = (const float*)d_in[5];
    float* out = (float*)d_out;

    const int B = in_sizes[0] / SEQLEN;
    const int threads = 128;
    const int blocks = (B + threads - 1) / threads;
    rnn_modrelu_kernel<<<blocks, threads>>>(inputs, W_ih, W_hh, b_mod, W_lin, b_lin, out, B);
}